// round 2
// baseline (speedup 1.0000x reference)
#include <cuda_runtime.h>
#include <cstdio>

#define TSEQ 512
#define BB 16          // batch elements per CTA
#define H 64
#define G 256          // 4*H gate columns
#define NTHREADS 256
#define BATCH 2048
#define NBLOCKS (BATCH / BB)   // 128

// smem layout (floats)
#define OFF_WT0   0
#define OFF_WIT1  16384
#define OFF_WHT1  32768
#define OFF_GBUF  49152          // [BB][256]
#define OFF_H0    (49152+4096)   // [BB][64]
#define OFF_H1    (OFF_H0+1024)
#define OFF_XB    (OFF_H1+1024)  // [BB]
#define SMEM_FLOATS (OFF_XB + 16)
#define SMEM_BYTES  (SMEM_FLOATS * 4)   // 221248

__device__ __forceinline__ float fast_ex2(float x){ float y; asm("ex2.approx.f32 %0, %1;" : "=f"(y) : "f"(x)); return y; }
__device__ __forceinline__ float fast_rcp(float x){ float y; asm("rcp.approx.f32 %0, %1;" : "=f"(y) : "f"(x)); return y; }

// sigmoid(v) = 1/(1+exp(-v)) via ex2: rel err ~1e-7
__device__ __forceinline__ float sigm_(float v){
    float e = fast_ex2(-1.4426950408889634f * v);
    return fast_rcp(1.0f + e);
}
// tanh(v) = (1-exp(-2v))/(1+exp(-2v)); clamp to avoid ex2 overflow -> NaN
__device__ __forceinline__ float tanh_(float v){
    v = fminf(fmaxf(v, -40.0f), 40.0f);
    float e = fast_ex2(-2.8853900817779268f * v);
    return (1.0f - e) * fast_rcp(1.0f + e);
}

__global__ __launch_bounds__(NTHREADS, 1)
void lstm2_fused_kernel(const float* __restrict__ x,
                        const float* __restrict__ w_ih0, const float* __restrict__ w_hh0,
                        const float* __restrict__ b_ih0, const float* __restrict__ b_hh0,
                        const float* __restrict__ w_ih1, const float* __restrict__ w_hh1,
                        const float* __restrict__ b_ih1, const float* __restrict__ b_hh1,
                        const float* __restrict__ w_fc,  const float* __restrict__ b_fc,
                        float* __restrict__ out)
{
    extern __shared__ float smem[];
    float* WT0  = smem + OFF_WT0;    // [k=64][j=256], WT0[k*256+j] = w_hh0[j*64+k]
    float* WIT1 = smem + OFF_WIT1;
    float* WHT1 = smem + OFF_WHT1;
    float* gbuf = smem + OFF_GBUF;   // activated gates [bb][256]
    float* h0s  = smem + OFF_H0;     // [bb][64]
    float* h1s  = smem + OFF_H1;
    float* xbuf = smem + OFF_XB;     // [bb]

    const int tid = threadIdx.x;
    const int bbase = blockIdx.x * BB;

    // load weights transposed into smem (one-time; L2-cached across CTAs)
    for (int idx = tid; idx < 64 * 256; idx += NTHREADS) {
        int k = idx >> 8, j = idx & 255;
        WT0[idx]  = w_hh0[j * 64 + k];
        WIT1[idx] = w_ih1[j * 64 + k];
        WHT1[idx] = w_hh1[j * 64 + k];
    }
    for (int idx = tid; idx < BB * 64; idx += NTHREADS) { h0s[idx] = 0.0f; h1s[idx] = 0.0f; }

    // per-thread constants: thread tid owns gate column j = tid
    const float wi0   = w_ih0[tid];            // input_dim = 1
    const float bias0 = b_ih0[tid] + b_hh0[tid];
    const float bias1 = b_ih1[tid] + b_hh1[tid];
    const int   gtype = tid >> 6;              // 0:i 1:f 2:g 3:o  (uniform per warp)

    // state-update mapping: thread handles 4 consecutive hidden units of one batch elem
    const int bb_u = tid >> 4;
    const int m_u  = (tid & 15) * 4;
    float4 c0 = make_float4(0.f, 0.f, 0.f, 0.f);
    float4 c1 = make_float4(0.f, 0.f, 0.f, 0.f);

    __syncthreads();

    for (int t = 0; t < TSEQ; ++t) {
        if (tid < BB) xbuf[tid] = x[(bbase + tid) * TSEQ + t];
        __syncthreads();

        float acc[BB];

        // ---------------- layer 0 gates: bias + x*w_ih + h0 . Whh0 ----------------
        #pragma unroll
        for (int bb = 0; bb < BB; ++bb) acc[bb] = fmaf(xbuf[bb], wi0, bias0);

        #pragma unroll 4
        for (int k = 0; k < 64; k += 4) {
            float w0 = WT0[(k + 0) * 256 + tid];
            float w1 = WT0[(k + 1) * 256 + tid];
            float w2 = WT0[(k + 2) * 256 + tid];
            float w3 = WT0[(k + 3) * 256 + tid];
            #pragma unroll
            for (int bb = 0; bb < BB; ++bb) {
                float4 h = *(const float4*)&h0s[bb * 64 + k];
                acc[bb] = fmaf(h.x, w0, acc[bb]);
                acc[bb] = fmaf(h.y, w1, acc[bb]);
                acc[bb] = fmaf(h.z, w2, acc[bb]);
                acc[bb] = fmaf(h.w, w3, acc[bb]);
            }
        }
        #pragma unroll
        for (int bb = 0; bb < BB; ++bb) {
            float v = acc[bb];
            v = (gtype == 2) ? tanh_(v) : sigm_(v);
            gbuf[bb * 256 + tid] = v;
        }
        __syncthreads();

        // ---------------- layer 0 state update ----------------
        {
            const float* gb = &gbuf[bb_u * 256 + m_u];
            float4 iv = *(const float4*)&gb[0];
            float4 fv = *(const float4*)&gb[64];
            float4 gv = *(const float4*)&gb[128];
            float4 ov = *(const float4*)&gb[192];
            c0.x = fmaf(fv.x, c0.x, iv.x * gv.x);
            c0.y = fmaf(fv.y, c0.y, iv.y * gv.y);
            c0.z = fmaf(fv.z, c0.z, iv.z * gv.z);
            c0.w = fmaf(fv.w, c0.w, iv.w * gv.w);
            float4 hv;
            hv.x = ov.x * tanh_(c0.x);
            hv.y = ov.y * tanh_(c0.y);
            hv.z = ov.z * tanh_(c0.z);
            hv.w = ov.w * tanh_(c0.w);
            *(float4*)&h0s[bb_u * 64 + m_u] = hv;
        }
        __syncthreads();

        // ---------------- layer 1 gates: bias + h0 . Wih1 + h1 . Whh1 ----------------
        #pragma unroll
        for (int bb = 0; bb < BB; ++bb) acc[bb] = bias1;

        #pragma unroll 2
        for (int k = 0; k < 64; k += 4) {
            float a0 = WIT1[(k + 0) * 256 + tid];
            float a1 = WIT1[(k + 1) * 256 + tid];
            float a2 = WIT1[(k + 2) * 256 + tid];
            float a3 = WIT1[(k + 3) * 256 + tid];
            float w0 = WHT1[(k + 0) * 256 + tid];
            float w1 = WHT1[(k + 1) * 256 + tid];
            float w2 = WHT1[(k + 2) * 256 + tid];
            float w3 = WHT1[(k + 3) * 256 + tid];
            #pragma unroll
            for (int bb = 0; bb < BB; ++bb) {
                float4 ha = *(const float4*)&h0s[bb * 64 + k];
                float4 hb = *(const float4*)&h1s[bb * 64 + k];
                acc[bb] = fmaf(ha.x, a0, acc[bb]);
                acc[bb] = fmaf(ha.y, a1, acc[bb]);
                acc[bb] = fmaf(ha.z, a2, acc[bb]);
                acc[bb] = fmaf(ha.w, a3, acc[bb]);
                acc[bb] = fmaf(hb.x, w0, acc[bb]);
                acc[bb] = fmaf(hb.y, w1, acc[bb]);
                acc[bb] = fmaf(hb.z, w2, acc[bb]);
                acc[bb] = fmaf(hb.w, w3, acc[bb]);
            }
        }
        #pragma unroll
        for (int bb = 0; bb < BB; ++bb) {
            float v = acc[bb];
            v = (gtype == 2) ? tanh_(v) : sigm_(v);
            gbuf[bb * 256 + tid] = v;
        }
        __syncthreads();

        // ---------------- layer 1 state update ----------------
        {
            const float* gb = &gbuf[bb_u * 256 + m_u];
            float4 iv = *(const float4*)&gb[0];
            float4 fv = *(const float4*)&gb[64];
            float4 gv = *(const float4*)&gb[128];
            float4 ov = *(const float4*)&gb[192];
            c1.x = fmaf(fv.x, c1.x, iv.x * gv.x);
            c1.y = fmaf(fv.y, c1.y, iv.y * gv.y);
            c1.z = fmaf(fv.z, c1.z, iv.z * gv.z);
            c1.w = fmaf(fv.w, c1.w, iv.w * gv.w);
            float4 hv;
            hv.x = ov.x * tanh_(c1.x);
            hv.y = ov.y * tanh_(c1.y);
            hv.z = ov.z * tanh_(c1.z);
            hv.w = ov.w * tanh_(c1.w);
            *(float4*)&h1s[bb_u * 64 + m_u] = hv;
        }
        __syncthreads();
    }

    // ---------------- final FC: out[b][cls] = h1 . w_fc[cls] + b_fc[cls] ----------------
    if (tid < BB * 3) {
        int bb  = tid / 3;
        int cls = tid - bb * 3;
        float s = b_fc[cls];
        #pragma unroll 8
        for (int m = 0; m < 64; ++m)
            s = fmaf(h1s[bb * 64 + m], w_fc[cls * 64 + m], s);
        out[(bbase + bb) * 3 + cls] = s;
    }
}

extern "C" void kernel_launch(void* const* d_in, const int* in_sizes, int n_in,
                              void* d_out, int out_size)
{
    const float* x     = (const float*)d_in[0];
    const float* w_ih0 = (const float*)d_in[1];
    const float* w_hh0 = (const float*)d_in[2];
    const float* b_ih0 = (const float*)d_in[3];
    const float* b_hh0 = (const float*)d_in[4];
    const float* w_ih1 = (const float*)d_in[5];
    const float* w_hh1 = (const float*)d_in[6];
    const float* b_ih1 = (const float*)d_in[7];
    const float* b_hh1 = (const float*)d_in[8];
    const float* w_fc  = (const float*)d_in[9];
    const float* b_fc  = (const float*)d_in[10];
    float* out = (float*)d_out;

    cudaFuncSetAttribute(lstm2_fused_kernel,
                         cudaFuncAttributeMaxDynamicSharedMemorySize, SMEM_BYTES);

    lstm2_fused_kernel<<<NBLOCKS, NTHREADS, SMEM_BYTES>>>(
        x, w_ih0, w_hh0, b_ih0, b_hh0,
        w_ih1, w_hh1, b_ih1, b_hh1,
        w_fc, b_fc, out);
}

// round 3
// speedup vs baseline: 1.3332x; 1.3332x over previous
#include <cuda_runtime.h>

#define TSEQ 512
#define BB 16
#define NTHREADS 256
#define BATCH 2048
#define NBLOCKS (BATCH / BB)   // 128

// smem layout (float indices)
#define OFF_W0   0          // [k=64][j=256]
#define OFF_WI1  16384
#define OFF_WH1  32768
#define OFF_GB   49152      // gbuf [BB][256]
#define OFF_H0D  53248      // h0 dup'd: BB*64 ull = 2048 floats
#define OFF_H1D  55296
#define OFF_XB   57344      // [BB]
#define SMEM_FLOATS (OFF_XB + 16)
#define SMEM_BYTES  (SMEM_FLOATS * 4)   // 229440 < 227KB limit

typedef unsigned long long ull;

__device__ __forceinline__ ull pack2(float lo, float hi){
    ull r; asm("mov.b64 %0, {%1,%2};" : "=l"(r) : "f"(lo), "f"(hi)); return r;
}
__device__ __forceinline__ void unpack2(ull v, float& lo, float& hi){
    asm("mov.b64 {%0,%1}, %2;" : "=f"(lo), "=f"(hi) : "l"(v));
}
__device__ __forceinline__ ull dup2(float v){ return pack2(v, v); }
__device__ __forceinline__ ull ffma2(ull a, ull b, ull c){
    ull d; asm("fma.rn.f32x2 %0, %1, %2, %3;" : "=l"(d) : "l"(a), "l"(b), "l"(c)); return d;
}
__device__ __forceinline__ float fast_ex2(float x){ float y; asm("ex2.approx.f32 %0, %1;" : "=f"(y) : "f"(x)); return y; }
__device__ __forceinline__ float fast_rcp(float x){ float y; asm("rcp.approx.f32 %0, %1;" : "=f"(y) : "f"(x)); return y; }

// sigmoid(v) = 1/(1+2^(-log2e*v))
__device__ __forceinline__ float sigm_(float v){
    float e = fast_ex2(-1.4426950408889634f * v);
    return fast_rcp(1.0f + e);
}
// tanh(v) = 2*sigmoid(2v)-1 (branchless)
__device__ __forceinline__ float tanh_(float v){
    float e = fast_ex2(-2.8853900817779268f * v);
    return fmaf(2.0f, fast_rcp(1.0f + e), -1.0f);
}

// accumulate acc[cp][bb] += sum_k hdup[bb][k] * W[k][j0+2cp..+1]
__device__ __forceinline__ void gemm_k64(ull acc[2][4], const float* __restrict__ W,
                                         const ull* __restrict__ hd, int j0)
{
    #pragma unroll 8
    for (int k = 0; k < 64; k += 2) {
        ulonglong2 w0 = *(const ulonglong2*)(W + k * 256 + j0);        // (wj0,wj1),(wj2,wj3) @ k
        ulonglong2 w1 = *(const ulonglong2*)(W + (k + 1) * 256 + j0);  // @ k+1
        #pragma unroll
        for (int bb = 0; bb < 4; ++bb) {
            ulonglong2 hp = *(const ulonglong2*)(hd + bb * 64 + k);    // (h[k],h[k]),(h[k+1],h[k+1])
            acc[0][bb] = ffma2(hp.x, w0.x, acc[0][bb]);
            acc[1][bb] = ffma2(hp.x, w0.y, acc[1][bb]);
            acc[0][bb] = ffma2(hp.y, w1.x, acc[0][bb]);
            acc[1][bb] = ffma2(hp.y, w1.y, acc[1][bb]);
        }
    }
}

__global__ __launch_bounds__(NTHREADS, 1)
void lstm2_fused_kernel(const float* __restrict__ x,
                        const float* __restrict__ w_ih0, const float* __restrict__ w_hh0,
                        const float* __restrict__ b_ih0, const float* __restrict__ b_hh0,
                        const float* __restrict__ w_ih1, const float* __restrict__ w_hh1,
                        const float* __restrict__ b_ih1, const float* __restrict__ b_hh1,
                        const float* __restrict__ w_fc,  const float* __restrict__ b_fc,
                        float* __restrict__ out)
{
    extern __shared__ float smem[];
    float* W0   = smem + OFF_W0;
    float* WI1  = smem + OFF_WI1;
    float* WH1  = smem + OFF_WH1;
    float* gbuf = smem + OFF_GB;
    ull*   h0d  = (ull*)(smem + OFF_H0D);
    ull*   h1d  = (ull*)(smem + OFF_H1D);
    float* xbuf = smem + OFF_XB;

    const int tid   = threadIdx.x;
    const int bbase = blockIdx.x * BB;

    // load weights transposed: W[k][j] = w[j*64+k]
    for (int idx = tid; idx < 64 * 256; idx += NTHREADS) {
        int k = idx >> 8, j = idx & 255;
        W0[idx]  = w_hh0[j * 64 + k];
        WI1[idx] = w_ih1[j * 64 + k];
        WH1[idx] = w_hh1[j * 64 + k];
    }
    for (int idx = tid; idx < BB * 64; idx += NTHREADS) { h0d[idx] = 0ULL; h1d[idx] = 0ULL; }
    if (tid < BB) xbuf[tid] = x[(bbase + tid) * TSEQ + 0];

    // thread tiling: 4 gate columns x 4 batch elems
    const int cg = tid & 63;           // column group -> cols j0..j0+3
    const int bg = tid >> 6;           // batch group  -> bb 4bg..4bg+3
    const int j0 = cg * 4;
    const int g  = cg >> 4;            // gate type 0:i 1:f 2:g 3:o
    const float kexp = (g == 2) ? -2.8853900817779268f : -1.4426950408889634f;
    const float amul = (g == 2) ? 2.0f : 1.0f;
    const float aadd = (g == 2) ? -1.0f : 0.0f;

    ull bias0p[2], bias1p[2], wi0p[2];
    #pragma unroll
    for (int cp = 0; cp < 2; ++cp) {
        int ja = j0 + 2 * cp, jb = ja + 1;
        bias0p[cp] = pack2(b_ih0[ja] + b_hh0[ja], b_ih0[jb] + b_hh0[jb]);
        bias1p[cp] = pack2(b_ih1[ja] + b_hh1[ja], b_ih1[jb] + b_hh1[jb]);
        wi0p[cp]   = pack2(w_ih0[ja], w_ih0[jb]);
    }

    // state-update mapping: thread -> (batch bb_u, 4 hidden units m_u..m_u+3)
    const int bb_u = tid >> 4;
    const int m_u  = (tid & 15) * 4;
    float4 c0 = make_float4(0.f, 0.f, 0.f, 0.f);
    float4 c1 = make_float4(0.f, 0.f, 0.f, 0.f);

    const ull* hrd = h0d + bg * 256;   // this thread's 4 batch rows (64 ull each)
    const ull* hrd1 = h1d + bg * 256;
    float* gwr = gbuf + bg * 4 * 256 + j0;

    __syncthreads();

    for (int t = 0; t < TSEQ; ++t) {
        ull acc[2][4];

        // ---- layer 0 gates ----
        #pragma unroll
        for (int bb = 0; bb < 4; ++bb) {
            ull xd = dup2(xbuf[bg * 4 + bb]);
            acc[0][bb] = ffma2(xd, wi0p[0], bias0p[0]);
            acc[1][bb] = ffma2(xd, wi0p[1], bias0p[1]);
        }
        gemm_k64(acc, W0, hrd, j0);

        #pragma unroll
        for (int bb = 0; bb < 4; ++bb) {
            float a0, a1, a2, a3;
            unpack2(acc[0][bb], a0, a1);
            unpack2(acc[1][bb], a2, a3);
            float4 gv;
            gv.x = fmaf(amul, fast_rcp(1.0f + fast_ex2(kexp * a0)), aadd);
            gv.y = fmaf(amul, fast_rcp(1.0f + fast_ex2(kexp * a1)), aadd);
            gv.z = fmaf(amul, fast_rcp(1.0f + fast_ex2(kexp * a2)), aadd);
            gv.w = fmaf(amul, fast_rcp(1.0f + fast_ex2(kexp * a3)), aadd);
            *(float4*)&gwr[bb * 256] = gv;
        }
        __syncthreads();

        // ---- layer 0 state update (writes h0d dup'd) ----
        {
            const float* gb = &gbuf[bb_u * 256 + m_u];
            float4 iv = *(const float4*)&gb[0];
            float4 fv = *(const float4*)&gb[64];
            float4 gv = *(const float4*)&gb[128];
            float4 ov = *(const float4*)&gb[192];
            c0.x = fmaf(fv.x, c0.x, iv.x * gv.x);
            c0.y = fmaf(fv.y, c0.y, iv.y * gv.y);
            c0.z = fmaf(fv.z, c0.z, iv.z * gv.z);
            c0.w = fmaf(fv.w, c0.w, iv.w * gv.w);
            float hx = ov.x * tanh_(c0.x);
            float hy = ov.y * tanh_(c0.y);
            float hz = ov.z * tanh_(c0.z);
            float hw = ov.w * tanh_(c0.w);
            ulonglong2 p0; p0.x = pack2(hx, hx); p0.y = pack2(hy, hy);
            ulonglong2 p1; p1.x = pack2(hz, hz); p1.y = pack2(hw, hw);
            *(ulonglong2*)&h0d[bb_u * 64 + m_u]     = p0;
            *(ulonglong2*)&h0d[bb_u * 64 + m_u + 2] = p1;
        }
        __syncthreads();

        // ---- layer 1 gates: bias + h0.Wih1 + h1.Whh1 ----
        #pragma unroll
        for (int cp = 0; cp < 2; ++cp)
            #pragma unroll
            for (int bb = 0; bb < 4; ++bb) acc[cp][bb] = bias1p[cp];
        gemm_k64(acc, WI1, hrd, j0);
        gemm_k64(acc, WH1, hrd1, j0);

        #pragma unroll
        for (int bb = 0; bb < 4; ++bb) {
            float a0, a1, a2, a3;
            unpack2(acc[0][bb], a0, a1);
            unpack2(acc[1][bb], a2, a3);
            float4 gv;
            gv.x = fmaf(amul, fast_rcp(1.0f + fast_ex2(kexp * a0)), aadd);
            gv.y = fmaf(amul, fast_rcp(1.0f + fast_ex2(kexp * a1)), aadd);
            gv.z = fmaf(amul, fast_rcp(1.0f + fast_ex2(kexp * a2)), aadd);
            gv.w = fmaf(amul, fast_rcp(1.0f + fast_ex2(kexp * a3)), aadd);
            *(float4*)&gwr[bb * 256] = gv;
        }
        __syncthreads();

        // ---- layer 1 state update (writes h1d dup'd) + prefetch next x ----
        {
            const float* gb = &gbuf[bb_u * 256 + m_u];
            float4 iv = *(const float4*)&gb[0];
            float4 fv = *(const float4*)&gb[64];
            float4 gv = *(const float4*)&gb[128];
            float4 ov = *(const float4*)&gb[192];
            c1.x = fmaf(fv.x, c1.x, iv.x * gv.x);
            c1.y = fmaf(fv.y, c1.y, iv.y * gv.y);
            c1.z = fmaf(fv.z, c1.z, iv.z * gv.z);
            c1.w = fmaf(fv.w, c1.w, iv.w * gv.w);
            float hx = ov.x * tanh_(c1.x);
            float hy = ov.y * tanh_(c1.y);
            float hz = ov.z * tanh_(c1.z);
            float hw = ov.w * tanh_(c1.w);
            ulonglong2 p0; p0.x = pack2(hx, hx); p0.y = pack2(hy, hy);
            ulonglong2 p1; p1.x = pack2(hz, hz); p1.y = pack2(hw, hw);
            *(ulonglong2*)&h1d[bb_u * 64 + m_u]     = p0;
            *(ulonglong2*)&h1d[bb_u * 64 + m_u + 2] = p1;
        }
        if (t + 1 < TSEQ && tid < BB) xbuf[tid] = x[(bbase + tid) * TSEQ + (t + 1)];
        __syncthreads();
    }

    // ---- final FC ----
    if (tid < BB * 3) {
        int bb  = tid / 3;
        int cls = tid - bb * 3;
        float s = b_fc[cls];
        const float* h1f = (const float*)(h1d + bb * 64);   // dup'd: lo at index 2m
        #pragma unroll 8
        for (int m = 0; m < 64; ++m)
            s = fmaf(h1f[2 * m], w_fc[cls * 64 + m], s);
        out[(bbase + bb) * 3 + cls] = s;
    }
}

extern "C" void kernel_launch(void* const* d_in, const int* in_sizes, int n_in,
                              void* d_out, int out_size)
{
    const float* x     = (const float*)d_in[0];
    const float* w_ih0 = (const float*)d_in[1];
    const float* w_hh0 = (const float*)d_in[2];
    const float* b_ih0 = (const float*)d_in[3];
    const float* b_hh0 = (const float*)d_in[4];
    const float* w_ih1 = (const float*)d_in[5];
    const float* w_hh1 = (const float*)d_in[6];
    const float* b_ih1 = (const float*)d_in[7];
    const float* b_hh1 = (const float*)d_in[8];
    const float* w_fc  = (const float*)d_in[9];
    const float* b_fc  = (const float*)d_in[10];
    float* out = (float*)d_out;

    cudaFuncSetAttribute(lstm2_fused_kernel,
                         cudaFuncAttributeMaxDynamicSharedMemorySize, SMEM_BYTES);

    lstm2_fused_kernel<<<NBLOCKS, NTHREADS, SMEM_BYTES>>>(
        x, w_ih0, w_hh0, b_ih0, b_hh0,
        w_ih1, w_hh1, b_ih1, b_hh1,
        w_fc, b_fc, out);
}

// round 4
// speedup vs baseline: 1.5260x; 1.1446x over previous
#include <cuda_runtime.h>

#define TSEQ 512
#define BB 16
#define NTHREADS 256
#define BATCH 2048
#define NBLOCKS (BATCH / BB)   // 128

// smem layout (float indices)
// weights interleaved over k-pairs: WP[k2][j][p] = w[j*64 + 2*k2 + p], k2=0..31
#define OFF_WP0   0
#define OFF_WPI1  16384
#define OFF_WPH1  32768
#define OFF_GB    49152      // gbuf [16][256]
#define OFF_H0    53248      // h0 [16][64]
#define OFF_H1    54272      // h1 [16][64]
#define OFF_XB    55296      // [16]
#define SMEM_FLOATS (OFF_XB + 16)
#define SMEM_BYTES  (SMEM_FLOATS * 4)   // 221248

typedef unsigned long long ull;

__device__ __forceinline__ ull pack2(float lo, float hi){
    ull r; asm("mov.b64 %0, {%1,%2};" : "=l"(r) : "f"(lo), "f"(hi)); return r;
}
__device__ __forceinline__ void unpack2(ull v, float& lo, float& hi){
    asm("mov.b64 {%0,%1}, %2;" : "=f"(lo), "=f"(hi) : "l"(v));
}
__device__ __forceinline__ ull ffma2(ull a, ull b, ull c){
    ull d; asm("fma.rn.f32x2 %0, %1, %2, %3;" : "=l"(d) : "l"(a), "l"(b), "l"(c)); return d;
}
__device__ __forceinline__ float fast_ex2(float x){ float y; asm("ex2.approx.f32 %0, %1;" : "=f"(y) : "f"(x)); return y; }
__device__ __forceinline__ float fast_rcp(float x){ float y; asm("rcp.approx.f32 %0, %1;" : "=f"(y) : "f"(x)); return y; }

__device__ __forceinline__ float tanh_(float v){
    float e = fast_ex2(-2.8853900817779268f * v);
    return fmaf(2.0f, fast_rcp(1.0f + e), -1.0f);
}

// acc[c][bb] (ull, k-even/k-odd split) += h[bg-rows] * WP cols j0..j0+1
// WP: [k2][256][2] interleaved; hrow: [8 rows][64] fp32 (this thread's batch slice)
__device__ __forceinline__ void gemm_k64(ull acc[2][8], const float* __restrict__ WP,
                                         const float* __restrict__ hrow, int j0)
{
    #pragma unroll 4
    for (int k4 = 0; k4 < 16; ++k4) {
        // two k-pairs: (4k4, 4k4+1) and (4k4+2, 4k4+3)
        ulonglong2 wa = *(const ulonglong2*)(WP + ((2 * k4) * 256 + j0) * 2);
        ulonglong2 wb = *(const ulonglong2*)(WP + ((2 * k4 + 1) * 256 + j0) * 2);
        #pragma unroll
        for (int bb = 0; bb < 8; ++bb) {
            ulonglong2 hv = *(const ulonglong2*)(hrow + bb * 64 + 4 * k4); // (h0,h1),(h2,h3) broadcast
            acc[0][bb] = ffma2(hv.x, wa.x, acc[0][bb]);
            acc[1][bb] = ffma2(hv.x, wa.y, acc[1][bb]);
            acc[0][bb] = ffma2(hv.y, wb.x, acc[0][bb]);
            acc[1][bb] = ffma2(hv.y, wb.y, acc[1][bb]);
        }
    }
}

__global__ __launch_bounds__(NTHREADS, 1)
void lstm2_fused_kernel(const float* __restrict__ x,
                        const float* __restrict__ w_ih0, const float* __restrict__ w_hh0,
                        const float* __restrict__ b_ih0, const float* __restrict__ b_hh0,
                        const float* __restrict__ w_ih1, const float* __restrict__ w_hh1,
                        const float* __restrict__ b_ih1, const float* __restrict__ b_hh1,
                        const float* __restrict__ w_fc,  const float* __restrict__ b_fc,
                        float* __restrict__ out)
{
    extern __shared__ float smem[];
    float* WP0  = smem + OFF_WP0;
    float* WPI1 = smem + OFF_WPI1;
    float* WPH1 = smem + OFF_WPH1;
    float* gbuf = smem + OFF_GB;
    float* h0s  = smem + OFF_H0;
    float* h1s  = smem + OFF_H1;
    float* xbuf = smem + OFF_XB;

    const int tid   = threadIdx.x;
    const int bbase = blockIdx.x * BB;

    // weights -> smem, k-pair interleaved: WP[(k2*256 + j)*2 + p] = w[j*64 + 2*k2 + p]
    for (int idx = tid; idx < 32 * 256; idx += NTHREADS) {
        int k2 = idx >> 8, j = idx & 255;
        float2 a0 = *(const float2*)(w_hh0 + j * 64 + 2 * k2);
        float2 a1 = *(const float2*)(w_ih1 + j * 64 + 2 * k2);
        float2 a2 = *(const float2*)(w_hh1 + j * 64 + 2 * k2);
        *(float2*)(WP0  + idx * 2) = a0;
        *(float2*)(WPI1 + idx * 2) = a1;
        *(float2*)(WPH1 + idx * 2) = a2;
    }
    for (int idx = tid; idx < BB * 64; idx += NTHREADS) { h0s[idx] = 0.0f; h1s[idx] = 0.0f; }
    if (tid < BB) xbuf[tid] = x[(bbase + tid) * TSEQ + 0];

    // tiling: 2 gate columns x 8 batch elems per thread
    const int cg = tid & 127;          // column group -> cols j0, j0+1
    const int bg = tid >> 7;           // batch half   -> bb = 8bg .. 8bg+7
    const int j0 = cg * 2;
    const int g  = cg >> 5;            // gate type, uniform per warp
    const float kexp = (g == 2) ? -2.8853900817779268f : -1.4426950408889634f;
    const float amul = (g == 2) ? 2.0f : 1.0f;
    const float aadd = (g == 2) ? -1.0f : 0.0f;

    float bias0c[2], bias1c[2], wi0c[2];
    #pragma unroll
    for (int c = 0; c < 2; ++c) {
        bias0c[c] = b_ih0[j0 + c] + b_hh0[j0 + c];
        bias1c[c] = b_ih1[j0 + c] + b_hh1[j0 + c];
        wi0c[c]   = w_ih0[j0 + c];
    }

    // state-update mapping
    const int bb_u = tid >> 4;
    const int m_u  = (tid & 15) * 4;
    float4 c0 = make_float4(0.f, 0.f, 0.f, 0.f);
    float4 c1 = make_float4(0.f, 0.f, 0.f, 0.f);

    const float* hrd0 = h0s + bg * 8 * 64;
    const float* hrd1 = h1s + bg * 8 * 64;
    float* gwr = gbuf + bg * 8 * 256 + j0;
    const float* xrd = xbuf + bg * 8;

    __syncthreads();

    for (int t = 0; t < TSEQ; ++t) {
        ull acc[2][8];

        // ---- layer 0 gates: h0 . Whh0 (bias + x*w folded into epilogue) ----
        #pragma unroll
        for (int c = 0; c < 2; ++c)
            #pragma unroll
            for (int bb = 0; bb < 8; ++bb) acc[c][bb] = 0ULL;
        gemm_k64(acc, WP0, hrd0, j0);

        #pragma unroll
        for (int bb = 0; bb < 8; ++bb) {
            float xv = xrd[bb];
            float2 gv;
            float lo, hi;
            unpack2(acc[0][bb], lo, hi);
            float v0 = fmaf(xv, wi0c[0], bias0c[0]) + (lo + hi);
            unpack2(acc[1][bb], lo, hi);
            float v1 = fmaf(xv, wi0c[1], bias0c[1]) + (lo + hi);
            gv.x = fmaf(amul, fast_rcp(1.0f + fast_ex2(kexp * v0)), aadd);
            gv.y = fmaf(amul, fast_rcp(1.0f + fast_ex2(kexp * v1)), aadd);
            *(float2*)&gwr[bb * 256] = gv;
        }
        __syncthreads();

        // ---- layer 0 state update ----
        {
            const float* gb = &gbuf[bb_u * 256 + m_u];
            float4 iv = *(const float4*)&gb[0];
            float4 fv = *(const float4*)&gb[64];
            float4 gv = *(const float4*)&gb[128];
            float4 ov = *(const float4*)&gb[192];
            c0.x = fmaf(fv.x, c0.x, iv.x * gv.x);
            c0.y = fmaf(fv.y, c0.y, iv.y * gv.y);
            c0.z = fmaf(fv.z, c0.z, iv.z * gv.z);
            c0.w = fmaf(fv.w, c0.w, iv.w * gv.w);
            float4 hv;
            hv.x = ov.x * tanh_(c0.x);
            hv.y = ov.y * tanh_(c0.y);
            hv.z = ov.z * tanh_(c0.z);
            hv.w = ov.w * tanh_(c0.w);
            *(float4*)&h0s[bb_u * 64 + m_u] = hv;
        }
        __syncthreads();

        // ---- layer 1 gates: h0 . Wih1 + h1 . Whh1 ----
        #pragma unroll
        for (int c = 0; c < 2; ++c)
            #pragma unroll
            for (int bb = 0; bb < 8; ++bb) acc[c][bb] = 0ULL;
        gemm_k64(acc, WPI1, hrd0, j0);
        gemm_k64(acc, WPH1, hrd1, j0);

        #pragma unroll
        for (int bb = 0; bb < 8; ++bb) {
            float2 gv;
            float lo, hi;
            unpack2(acc[0][bb], lo, hi);
            float v0 = bias1c[0] + (lo + hi);
            unpack2(acc[1][bb], lo, hi);
            float v1 = bias1c[1] + (lo + hi);
            gv.x = fmaf(amul, fast_rcp(1.0f + fast_ex2(kexp * v0)), aadd);
            gv.y = fmaf(amul, fast_rcp(1.0f + fast_ex2(kexp * v1)), aadd);
            *(float2*)&gwr[bb * 256] = gv;
        }
        __syncthreads();

        // ---- layer 1 state update + x prefetch ----
        {
            const float* gb = &gbuf[bb_u * 256 + m_u];
            float4 iv = *(const float4*)&gb[0];
            float4 fv = *(const float4*)&gb[64];
            float4 gv = *(const float4*)&gb[128];
            float4 ov = *(const float4*)&gb[192];
            c1.x = fmaf(fv.x, c1.x, iv.x * gv.x);
            c1.y = fmaf(fv.y, c1.y, iv.y * gv.y);
            c1.z = fmaf(fv.z, c1.z, iv.z * gv.z);
            c1.w = fmaf(fv.w, c1.w, iv.w * gv.w);
            float4 hv;
            hv.x = ov.x * tanh_(c1.x);
            hv.y = ov.y * tanh_(c1.y);
            hv.z = ov.z * tanh_(c1.z);
            hv.w = ov.w * tanh_(c1.w);
            *(float4*)&h1s[bb_u * 64 + m_u] = hv;
        }
        if (t + 1 < TSEQ && tid < BB) xbuf[tid] = x[(bbase + tid) * TSEQ + (t + 1)];
        __syncthreads();
    }

    // ---- final FC ----
    if (tid < BB * 3) {
        int bb  = tid / 3;
        int cls = tid - bb * 3;
        float s = b_fc[cls];
        #pragma unroll 8
        for (int m = 0; m < 64; ++m)
            s = fmaf(h1s[bb * 64 + m], w_fc[cls * 64 + m], s);
        out[(bbase + bb) * 3 + cls] = s;
    }
}

extern "C" void kernel_launch(void* const* d_in, const int* in_sizes, int n_in,
                              void* d_out, int out_size)
{
    const float* x     = (const float*)d_in[0];
    const float* w_ih0 = (const float*)d_in[1];
    const float* w_hh0 = (const float*)d_in[2];
    const float* b_ih0 = (const float*)d_in[3];
    const float* b_hh0 = (const float*)d_in[4];
    const float* w_ih1 = (const float*)d_in[5];
    const float* w_hh1 = (const float*)d_in[6];
    const float* b_ih1 = (const float*)d_in[7];
    const float* b_hh1 = (const float*)d_in[8];
    const float* w_fc  = (const float*)d_in[9];
    const float* b_fc  = (const float*)d_in[10];
    float* out = (float*)d_out;

    cudaFuncSetAttribute(lstm2_fused_kernel,
                         cudaFuncAttributeMaxDynamicSharedMemorySize, SMEM_BYTES);

    lstm2_fused_kernel<<<NBLOCKS, NTHREADS, SMEM_BYTES>>>(
        x, w_ih0, w_hh0, b_ih0, b_hh0,
        w_ih1, w_hh1, b_ih1, b_hh1,
        w_fc, b_fc, out);
}

// round 6
// speedup vs baseline: 1.7174x; 1.1254x over previous
#include <cuda_runtime.h>

#define TSEQ 512
#define BB 16
#define NTHREADS 256
#define BATCH 2048
#define NBLOCKS (BATCH / BB)   // 128

// smem layout (float indices)
// weights interleaved over k-pairs: WP[k2][j][p] = w[j*64 + 2*k2 + p], k2=0..31
#define OFF_WP0   0
#define OFF_WPI1  16384
#define OFF_WPH1  32768
#define OFF_GB    49152      // gbuf [16][256]
#define OFF_H0    53248      // h0 [16][64]
#define OFF_H1    54272      // h1 [16][64]
#define OFF_XB    55296      // [16]
#define SMEM_FLOATS (OFF_XB + 16)
#define SMEM_BYTES  (SMEM_FLOATS * 4)   // 221248

typedef unsigned long long ull;

__device__ __forceinline__ ull pack2(float lo, float hi){
    ull r; asm("mov.b64 %0, {%1,%2};" : "=l"(r) : "f"(lo), "f"(hi)); return r;
}
__device__ __forceinline__ void unpack2(ull v, float& lo, float& hi){
    asm("mov.b64 {%0,%1}, %2;" : "=f"(lo), "=f"(hi) : "l"(v));
}
__device__ __forceinline__ ull ffma2(ull a, ull b, ull c){
    ull d; asm("fma.rn.f32x2 %0, %1, %2, %3;" : "=l"(d) : "l"(a), "l"(b), "l"(c)); return d;
}
__device__ __forceinline__ float fast_ex2(float x){ float y; asm("ex2.approx.f32 %0, %1;" : "=f"(y) : "f"(x)); return y; }
__device__ __forceinline__ float fast_rcp(float x){ float y; asm("rcp.approx.f32 %0, %1;" : "=f"(y) : "f"(x)); return y; }

__device__ __forceinline__ float tanh_(float v){
    float e = fast_ex2(-2.8853900817779268f * v);
    return fmaf(2.0f, fast_rcp(1.0f + e), -1.0f);
}

// Software-pipelined: acc[c][bb] += sum_k h[bb][k] * W[k][j0+c]
// WP: [k2][256][2] interleaved (1024 floats per k4-block of 4 k's);
// hrow: [8 rows][64] fp32 broadcast.
__device__ __forceinline__ void gemm_k64(ull acc[2][8], const float* __restrict__ WP,
                                         const float* __restrict__ hrow, int j0)
{
    const float* wp = WP + j0 * 2;
    // prologue: weights for k4=0
    ulonglong2 wa = *(const ulonglong2*)(wp);
    ulonglong2 wb = *(const ulonglong2*)(wp + 512);
    const float* wpn = wp + 1024;

    #pragma unroll
    for (int k4 = 0; k4 < 16; ++k4) {
        // front-batch all h loads for this iteration (8 independent broadcast LDS.128)
        ulonglong2 hv[8];
        #pragma unroll
        for (int bb = 0; bb < 8; ++bb)
            hv[bb] = *(const ulonglong2*)(hrow + bb * 64 + 4 * k4);

        // prefetch next iteration's weights while FMAs below drain
        ulonglong2 wa_n, wb_n;
        if (k4 < 15) {
            wa_n = *(const ulonglong2*)(wpn);
            wb_n = *(const ulonglong2*)(wpn + 512);
        }
        wpn += 1024;

        #pragma unroll
        for (int bb = 0; bb < 8; ++bb) {
            acc[0][bb] = ffma2(hv[bb].x, wa.x, acc[0][bb]);
            acc[1][bb] = ffma2(hv[bb].x, wa.y, acc[1][bb]);
            acc[0][bb] = ffma2(hv[bb].y, wb.x, acc[0][bb]);
            acc[1][bb] = ffma2(hv[bb].y, wb.y, acc[1][bb]);
        }
        wa = wa_n; wb = wb_n;
    }
}

__global__ __launch_bounds__(NTHREADS)
void lstm2_fused_kernel(const float* __restrict__ x,
                        const float* __restrict__ w_ih0, const float* __restrict__ w_hh0,
                        const float* __restrict__ b_ih0, const float* __restrict__ b_hh0,
                        const float* __restrict__ w_ih1, const float* __restrict__ w_hh1,
                        const float* __restrict__ b_ih1, const float* __restrict__ b_hh1,
                        const float* __restrict__ w_fc,  const float* __restrict__ b_fc,
                        float* __restrict__ out)
{
    extern __shared__ float smem[];
    float* WP0  = smem + OFF_WP0;
    float* WPI1 = smem + OFF_WPI1;
    float* WPH1 = smem + OFF_WPH1;
    float* gbuf = smem + OFF_GB;
    float* h0s  = smem + OFF_H0;
    float* h1s  = smem + OFF_H1;
    float* xbuf = smem + OFF_XB;

    const int tid   = threadIdx.x;
    const int bbase = blockIdx.x * BB;

    // weights -> smem, k-pair interleaved: WP[(k2*256 + j)*2 + p] = w[j*64 + 2*k2 + p]
    for (int idx = tid; idx < 32 * 256; idx += NTHREADS) {
        int k2 = idx >> 8, j = idx & 255;
        float2 a0 = *(const float2*)(w_hh0 + j * 64 + 2 * k2);
        float2 a1 = *(const float2*)(w_ih1 + j * 64 + 2 * k2);
        float2 a2 = *(const float2*)(w_hh1 + j * 64 + 2 * k2);
        *(float2*)(WP0  + idx * 2) = a0;
        *(float2*)(WPI1 + idx * 2) = a1;
        *(float2*)(WPH1 + idx * 2) = a2;
    }
    for (int idx = tid; idx < BB * 64; idx += NTHREADS) { h0s[idx] = 0.0f; h1s[idx] = 0.0f; }
    if (tid < BB) xbuf[tid] = x[(bbase + tid) * TSEQ + 0];

    // tiling: 2 gate columns x 8 batch elems per thread
    const int cg = tid & 127;          // column group -> cols j0, j0+1
    const int bg = tid >> 7;           // batch half   -> bb = 8bg .. 8bg+7
    const int j0 = cg * 2;
    const int g  = cg >> 5;            // gate type, uniform per warp
    const float kexp = (g == 2) ? -2.8853900817779268f : -1.4426950408889634f;
    const float amul = (g == 2) ? 2.0f : 1.0f;
    const float aadd = (g == 2) ? -1.0f : 0.0f;

    float bias0c[2], bias1c[2], wi0c[2];
    #pragma unroll
    for (int c = 0; c < 2; ++c) {
        bias0c[c] = b_ih0[j0 + c] + b_hh0[j0 + c];
        bias1c[c] = b_ih1[j0 + c] + b_hh1[j0 + c];
        wi0c[c]   = w_ih0[j0 + c];
    }

    // state-update mapping
    const int bb_u = tid >> 4;
    const int m_u  = (tid & 15) * 4;
    float4 c0 = make_float4(0.f, 0.f, 0.f, 0.f);
    float4 c1 = make_float4(0.f, 0.f, 0.f, 0.f);

    const float* hrd0 = h0s + bg * 8 * 64;
    const float* hrd1 = h1s + bg * 8 * 64;
    float* gwr = gbuf + bg * 8 * 256 + j0;
    const float* xrd = xbuf + bg * 8;

    __syncthreads();

    for (int t = 0; t < TSEQ; ++t) {
        ull acc[2][8];

        // ---- layer 0 gates: h0 . Whh0 (bias + x*w folded into epilogue) ----
        #pragma unroll
        for (int c = 0; c < 2; ++c)
            #pragma unroll
            for (int bb = 0; bb < 8; ++bb) acc[c][bb] = 0ULL;
        gemm_k64(acc, WP0, hrd0, j0);

        #pragma unroll
        for (int bb = 0; bb < 8; ++bb) {
            float xv = xrd[bb];
            float2 gv;
            float lo, hi;
            unpack2(acc[0][bb], lo, hi);
            float v0 = fmaf(xv, wi0c[0], bias0c[0]) + (lo + hi);
            unpack2(acc[1][bb], lo, hi);
            float v1 = fmaf(xv, wi0c[1], bias0c[1]) + (lo + hi);
            gv.x = fmaf(amul, fast_rcp(1.0f + fast_ex2(kexp * v0)), aadd);
            gv.y = fmaf(amul, fast_rcp(1.0f + fast_ex2(kexp * v1)), aadd);
            *(float2*)&gwr[bb * 256] = gv;
        }
        __syncthreads();

        // ---- layer 0 state update ----
        {
            const float* gb = &gbuf[bb_u * 256 + m_u];
            float4 iv = *(const float4*)&gb[0];
            float4 fv = *(const float4*)&gb[64];
            float4 gv = *(const float4*)&gb[128];
            float4 ov = *(const float4*)&gb[192];
            c0.x = fmaf(fv.x, c0.x, iv.x * gv.x);
            c0.y = fmaf(fv.y, c0.y, iv.y * gv.y);
            c0.z = fmaf(fv.z, c0.z, iv.z * gv.z);
            c0.w = fmaf(fv.w, c0.w, iv.w * gv.w);
            float4 hv;
            hv.x = ov.x * tanh_(c0.x);
            hv.y = ov.y * tanh_(c0.y);
            hv.z = ov.z * tanh_(c0.z);
            hv.w = ov.w * tanh_(c0.w);
            *(float4*)&h0s[bb_u * 64 + m_u] = hv;
        }
        __syncthreads();

        // ---- layer 1 gates: h0 . Wih1 + h1 . Whh1 ----
        #pragma unroll
        for (int c = 0; c < 2; ++c)
            #pragma unroll
            for (int bb = 0; bb < 8; ++bb) acc[c][bb] = 0ULL;
        gemm_k64(acc, WPI1, hrd0, j0);
        gemm_k64(acc, WPH1, hrd1, j0);

        #pragma unroll
        for (int bb = 0; bb < 8; ++bb) {
            float2 gv;
            float lo, hi;
            unpack2(acc[0][bb], lo, hi);
            float v0 = bias1c[0] + (lo + hi);
            unpack2(acc[1][bb], lo, hi);
            float v1 = bias1c[1] + (lo + hi);
            gv.x = fmaf(amul, fast_rcp(1.0f + fast_ex2(kexp * v0)), aadd);
            gv.y = fmaf(amul, fast_rcp(1.0f + fast_ex2(kexp * v1)), aadd);
            *(float2*)&gwr[bb * 256] = gv;
        }
        __syncthreads();

        // ---- layer 1 state update + x prefetch ----
        {
            const float* gb = &gbuf[bb_u * 256 + m_u];
            float4 iv = *(const float4*)&gb[0];
            float4 fv = *(const float4*)&gb[64];
            float4 gv = *(const float4*)&gb[128];
            float4 ov = *(const float4*)&gb[192];
            c1.x = fmaf(fv.x, c1.x, iv.x * gv.x);
            c1.y = fmaf(fv.y, c1.y, iv.y * gv.y);
            c1.z = fmaf(fv.z, c1.z, iv.z * gv.z);
            c1.w = fmaf(fv.w, c1.w, iv.w * gv.w);
            float4 hv;
            hv.x = ov.x * tanh_(c1.x);
            hv.y = ov.y * tanh_(c1.y);
            hv.z = ov.z * tanh_(c1.z);
            hv.w = ov.w * tanh_(c1.w);
            *(float4*)&h1s[bb_u * 64 + m_u] = hv;
        }
        if (t + 1 < TSEQ && tid < BB) xbuf[tid] = x[(bbase + tid) * TSEQ + (t + 1)];
        __syncthreads();
    }

    // ---- final FC ----
    if (tid < BB * 3) {
        int bb  = tid / 3;
        int cls = tid - bb * 3;
        float s = b_fc[cls];
        #pragma unroll 8
        for (int m = 0; m < 64; ++m)
            s = fmaf(h1s[bb * 64 + m], w_fc[cls * 64 + m], s);
        out[(bbase + bb) * 3 + cls] = s;
    }
}

extern "C" void kernel_launch(void* const* d_in, const int* in_sizes, int n_in,
                              void* d_out, int out_size)
{
    const float* x     = (const float*)d_in[0];
    const float* w_ih0 = (const float*)d_in[1];
    const float* w_hh0 = (const float*)d_in[2];
    const float* b_ih0 = (const float*)d_in[3];
    const float* b_hh0 = (const float*)d_in[4];
    const float* w_ih1 = (const float*)d_in[5];
    const float* w_hh1 = (const float*)d_in[6];
    const float* b_ih1 = (const float*)d_in[7];
    const float* b_hh1 = (const float*)d_in[8];
    const float* w_fc  = (const float*)d_in[9];
    const float* b_fc  = (const float*)d_in[10];
    float* out = (float*)d_out;

    cudaFuncSetAttribute(lstm2_fused_kernel,
                         cudaFuncAttributeMaxDynamicSharedMemorySize, SMEM_BYTES);

    lstm2_fused_kernel<<<NBLOCKS, NTHREADS, SMEM_BYTES>>>(
        x, w_ih0, w_hh0, b_ih0, b_hh0,
        w_ih1, w_hh1, b_ih1, b_hh1,
        w_fc, b_fc, out);
}

// round 7
// speedup vs baseline: 1.7230x; 1.0033x over previous
#include <cuda_runtime.h>

#define TSEQ 512
#define BB 16
#define NTHREADS 256
#define BATCH 2048
#define NBLOCKS (BATCH / BB)   // 128

// smem layout (float indices)
// weights interleaved over k-pairs: WP[k2][j][p] = w[j*64 + 2*k2 + p], k2=0..31
#define OFF_WP0   0
#define OFF_WPI1  16384
#define OFF_WPH1  32768
#define OFF_GB    49152      // gbuf [16][256]
#define OFF_H0    53248      // h0 [16][64]
#define OFF_H1    54272      // h1 [16][64]
#define OFF_XB    55296      // [16]
#define SMEM_FLOATS (OFF_XB + 16)
#define SMEM_BYTES  (SMEM_FLOATS * 4)   // 221248

typedef unsigned long long ull;

__device__ __forceinline__ void unpack2(ull v, float& lo, float& hi){
    asm("mov.b64 {%0,%1}, %2;" : "=f"(lo), "=f"(hi) : "l"(v));
}
__device__ __forceinline__ ull ffma2(ull a, ull b, ull c){
    ull d; asm("fma.rn.f32x2 %0, %1, %2, %3;" : "=l"(d) : "l"(a), "l"(b), "l"(c)); return d;
}
__device__ __forceinline__ float fast_ex2(float x){ float y; asm("ex2.approx.f32 %0, %1;" : "=f"(y) : "f"(x)); return y; }
__device__ __forceinline__ float fast_rcp(float x){ float y; asm("rcp.approx.f32 %0, %1;" : "=f"(y) : "f"(x)); return y; }

__device__ __forceinline__ float tanh_(float v){
    float e = fast_ex2(-2.8853900817779268f * v);
    return fmaf(2.0f, fast_rcp(1.0f + e), -1.0f);
}

// half-CTA barrier: id 1 or 2, 128 threads
__device__ __forceinline__ void half_bar(int id){
    asm volatile("bar.sync %0, %1;" :: "r"(id), "r"(128) : "memory");
}

// Software-pipelined: acc[c][bb] += sum_k h[bb][k] * W[k][j0+c]
// WP: [k2][256][2] interleaved; hrow: [8 rows][64] fp32 broadcast.
__device__ __forceinline__ void gemm_k64(ull acc[2][8], const float* __restrict__ WP,
                                         const float* __restrict__ hrow, int j0)
{
    const float* wp = WP + j0 * 2;
    ulonglong2 wa = *(const ulonglong2*)(wp);
    ulonglong2 wb = *(const ulonglong2*)(wp + 512);
    const float* wpn = wp + 1024;

    #pragma unroll
    for (int k4 = 0; k4 < 16; ++k4) {
        ulonglong2 hv[8];
        #pragma unroll
        for (int bb = 0; bb < 8; ++bb)
            hv[bb] = *(const ulonglong2*)(hrow + bb * 64 + 4 * k4);

        ulonglong2 wa_n, wb_n;
        if (k4 < 15) {
            wa_n = *(const ulonglong2*)(wpn);
            wb_n = *(const ulonglong2*)(wpn + 512);
        }
        wpn += 1024;

        #pragma unroll
        for (int bb = 0; bb < 8; ++bb) {
            acc[0][bb] = ffma2(hv[bb].x, wa.x, acc[0][bb]);
            acc[1][bb] = ffma2(hv[bb].x, wa.y, acc[1][bb]);
            acc[0][bb] = ffma2(hv[bb].y, wb.x, acc[0][bb]);
            acc[1][bb] = ffma2(hv[bb].y, wb.y, acc[1][bb]);
        }
        wa = wa_n; wb = wb_n;
    }
}

__global__ __launch_bounds__(NTHREADS)
void lstm2_fused_kernel(const float* __restrict__ x,
                        const float* __restrict__ w_ih0, const float* __restrict__ w_hh0,
                        const float* __restrict__ b_ih0, const float* __restrict__ b_hh0,
                        const float* __restrict__ w_ih1, const float* __restrict__ w_hh1,
                        const float* __restrict__ b_ih1, const float* __restrict__ b_hh1,
                        const float* __restrict__ w_fc,  const float* __restrict__ b_fc,
                        float* __restrict__ out)
{
    extern __shared__ float smem[];
    float* WP0  = smem + OFF_WP0;
    float* WPI1 = smem + OFF_WPI1;
    float* WPH1 = smem + OFF_WPH1;
    float* gbuf = smem + OFF_GB;
    float* h0s  = smem + OFF_H0;
    float* h1s  = smem + OFF_H1;
    float* xbuf = smem + OFF_XB;

    const int tid   = threadIdx.x;
    const int bbase = blockIdx.x * BB;

    // weights -> smem, k-pair interleaved: WP[(k2*256 + j)*2 + p] = w[j*64 + 2*k2 + p]
    for (int idx = tid; idx < 32 * 256; idx += NTHREADS) {
        int k2 = idx >> 8, j = idx & 255;
        float2 a0 = *(const float2*)(w_hh0 + j * 64 + 2 * k2);
        float2 a1 = *(const float2*)(w_ih1 + j * 64 + 2 * k2);
        float2 a2 = *(const float2*)(w_hh1 + j * 64 + 2 * k2);
        *(float2*)(WP0  + idx * 2) = a0;
        *(float2*)(WPI1 + idx * 2) = a1;
        *(float2*)(WPH1 + idx * 2) = a2;
    }
    for (int idx = tid; idx < BB * 64; idx += NTHREADS) { h0s[idx] = 0.0f; h1s[idx] = 0.0f; }
    if (tid < BB) xbuf[tid] = x[(bbase + tid) * TSEQ + 0];

    // half-CTA decomposition: warps 0-3 own bb 0-7, warps 4-7 own bb 8-15
    const int half = tid >> 7;         // 0 or 1
    const int l    = tid & 127;        // lane within half
    const int barid = half + 1;        // named barrier id

    // gemm tiling within half: 2 gate columns x 8 batch elems per thread
    const int j0 = l * 2;              // cols j0, j0+1 (l covers all 128 col-pairs)
    const int g  = l >> 5;             // gate type, uniform per warp
    const float kexp = (g == 2) ? -2.8853900817779268f : -1.4426950408889634f;
    const float amul = (g == 2) ? 2.0f : 1.0f;
    const float aadd = (g == 2) ? -1.0f : 0.0f;

    float bias0c[2], bias1c[2], wi0c[2];
    #pragma unroll
    for (int c = 0; c < 2; ++c) {
        bias0c[c] = b_ih0[j0 + c] + b_hh0[j0 + c];
        bias1c[c] = b_ih1[j0 + c] + b_hh1[j0 + c];
        wi0c[c]   = w_ih0[j0 + c];
    }

    // state-update mapping within half: 8 bb x 16 threads x 4 units
    const int bb_u = half * 8 + (l >> 4);
    const int m_u  = (l & 15) * 4;
    float4 c0 = make_float4(0.f, 0.f, 0.f, 0.f);
    float4 c1 = make_float4(0.f, 0.f, 0.f, 0.f);

    const float* hrd0 = h0s + half * 512;   // this half's 8 rows of h0
    const float* hrd1 = h1s + half * 512;
    float* gwr = gbuf + half * 8 * 256 + j0;
    const float* xrd = xbuf + half * 8;

    __syncthreads();

    for (int t = 0; t < TSEQ; ++t) {
        ull acc[2][8];

        // ---- layer 0 gates: h0 . Whh0 (bias + x*w folded into epilogue) ----
        #pragma unroll
        for (int c = 0; c < 2; ++c)
            #pragma unroll
            for (int bb = 0; bb < 8; ++bb) acc[c][bb] = 0ULL;
        gemm_k64(acc, WP0, hrd0, j0);

        #pragma unroll
        for (int bb = 0; bb < 8; ++bb) {
            float xv = xrd[bb];
            float2 gv;
            float lo, hi;
            unpack2(acc[0][bb], lo, hi);
            float v0 = fmaf(xv, wi0c[0], bias0c[0]) + (lo + hi);
            unpack2(acc[1][bb], lo, hi);
            float v1 = fmaf(xv, wi0c[1], bias0c[1]) + (lo + hi);
            gv.x = fmaf(amul, fast_rcp(1.0f + fast_ex2(kexp * v0)), aadd);
            gv.y = fmaf(amul, fast_rcp(1.0f + fast_ex2(kexp * v1)), aadd);
            *(float2*)&gwr[bb * 256] = gv;
        }
        half_bar(barid);

        // ---- layer 0 state update ----
        {
            const float* gb = &gbuf[bb_u * 256 + m_u];
            float4 iv = *(const float4*)&gb[0];
            float4 fv = *(const float4*)&gb[64];
            float4 gv = *(const float4*)&gb[128];
            float4 ov = *(const float4*)&gb[192];
            c0.x = fmaf(fv.x, c0.x, iv.x * gv.x);
            c0.y = fmaf(fv.y, c0.y, iv.y * gv.y);
            c0.z = fmaf(fv.z, c0.z, iv.z * gv.z);
            c0.w = fmaf(fv.w, c0.w, iv.w * gv.w);
            float4 hv;
            hv.x = ov.x * tanh_(c0.x);
            hv.y = ov.y * tanh_(c0.y);
            hv.z = ov.z * tanh_(c0.z);
            hv.w = ov.w * tanh_(c0.w);
            *(float4*)&h0s[bb_u * 64 + m_u] = hv;
        }
        half_bar(barid);

        // ---- layer 1 gates: h0 . Wih1 + h1 . Whh1 ----
        #pragma unroll
        for (int c = 0; c < 2; ++c)
            #pragma unroll
            for (int bb = 0; bb < 8; ++bb) acc[c][bb] = 0ULL;
        gemm_k64(acc, WPI1, hrd0, j0);
        gemm_k64(acc, WPH1, hrd1, j0);

        #pragma unroll
        for (int bb = 0; bb < 8; ++bb) {
            float2 gv;
            float lo, hi;
            unpack2(acc[0][bb], lo, hi);
            float v0 = bias1c[0] + (lo + hi);
            unpack2(acc[1][bb], lo, hi);
            float v1 = bias1c[1] + (lo + hi);
            gv.x = fmaf(amul, fast_rcp(1.0f + fast_ex2(kexp * v0)), aadd);
            gv.y = fmaf(amul, fast_rcp(1.0f + fast_ex2(kexp * v1)), aadd);
            *(float2*)&gwr[bb * 256] = gv;
        }
        half_bar(barid);

        // ---- layer 1 state update + x prefetch (half-local) ----
        {
            const float* gb = &gbuf[bb_u * 256 + m_u];
            float4 iv = *(const float4*)&gb[0];
            float4 fv = *(const float4*)&gb[64];
            float4 gv = *(const float4*)&gb[128];
            float4 ov = *(const float4*)&gb[192];
            c1.x = fmaf(fv.x, c1.x, iv.x * gv.x);
            c1.y = fmaf(fv.y, c1.y, iv.y * gv.y);
            c1.z = fmaf(fv.z, c1.z, iv.z * gv.z);
            c1.w = fmaf(fv.w, c1.w, iv.w * gv.w);
            float4 hv;
            hv.x = ov.x * tanh_(c1.x);
            hv.y = ov.y * tanh_(c1.y);
            hv.z = ov.z * tanh_(c1.z);
            hv.w = ov.w * tanh_(c1.w);
            *(float4*)&h1s[bb_u * 64 + m_u] = hv;
        }
        if (t + 1 < TSEQ && l < 8)
            xbuf[half * 8 + l] = x[(bbase + half * 8 + l) * TSEQ + (t + 1)];
        half_bar(barid);
    }

    // FC reads h1s across both halves -> full-CTA sync
    __syncthreads();

    // ---- final FC ----
    if (tid < BB * 3) {
        int bb  = tid / 3;
        int cls = tid - bb * 3;
        float s = b_fc[cls];
        #pragma unroll 8
        for (int m = 0; m < 64; ++m)
            s = fmaf(h1s[bb * 64 + m], w_fc[cls * 64 + m], s);
        out[(bbase + bb) * 3 + cls] = s;
    }
}

extern "C" void kernel_launch(void* const* d_in, const int* in_sizes, int n_in,
                              void* d_out, int out_size)
{
    const float* x     = (const float*)d_in[0];
    const float* w_ih0 = (const float*)d_in[1];
    const float* w_hh0 = (const float*)d_in[2];
    const float* b_ih0 = (const float*)d_in[3];
    const float* b_hh0 = (const float*)d_in[4];
    const float* w_ih1 = (const float*)d_in[5];
    const float* w_hh1 = (const float*)d_in[6];
    const float* b_ih1 = (const float*)d_in[7];
    const float* b_hh1 = (const float*)d_in[8];
    const float* w_fc  = (const float*)d_in[9];
    const float* b_fc  = (const float*)d_in[10];
    float* out = (float*)d_out;

    cudaFuncSetAttribute(lstm2_fused_kernel,
                         cudaFuncAttributeMaxDynamicSharedMemorySize, SMEM_BYTES);

    lstm2_fused_kernel<<<NBLOCKS, NTHREADS, SMEM_BYTES>>>(
        x, w_ih0, w_hh0, b_ih0, b_hh0,
        w_ih1, w_hh1, b_ih1, b_hh1,
        w_fc, b_fc, out);
}

// round 8
// speedup vs baseline: 1.7272x; 1.0025x over previous
#include <cuda_runtime.h>

#define TSEQ 512
#define BB 16
#define NTHREADS 256
#define BATCH 2048
#define NBLOCKS (BATCH / BB)   // 128

// smem layout (float indices)
// weights interleaved over k-pairs: WP[k2][j][p] = w[j*64 + 2*k2 + p], k2=0..31
#define OFF_WP0   0
#define OFF_WPI1  16384
#define OFF_WPH1  32768
#define OFF_GB    49152      // gbuf [16][256]
#define OFF_H0    53248      // h0 [16][64]
#define OFF_H1    54272      // h1 [16][64]
#define OFF_XB    55296      // [16]
#define SMEM_FLOATS (OFF_XB + 16)
#define SMEM_BYTES  (SMEM_FLOATS * 4)   // 221248

typedef unsigned long long ull;

__device__ __forceinline__ void unpack2(ull v, float& lo, float& hi){
    asm("mov.b64 {%0,%1}, %2;" : "=f"(lo), "=f"(hi) : "l"(v));
}
__device__ __forceinline__ ull ffma2(ull a, ull b, ull c){
    ull d; asm("fma.rn.f32x2 %0, %1, %2, %3;" : "=l"(d) : "l"(a), "l"(b), "l"(c)); return d;
}
__device__ __forceinline__ float fast_ex2(float x){ float y; asm("ex2.approx.f32 %0, %1;" : "=f"(y) : "f"(x)); return y; }
__device__ __forceinline__ float fast_rcp(float x){ float y; asm("rcp.approx.f32 %0, %1;" : "=f"(y) : "f"(x)); return y; }

__device__ __forceinline__ float tanh_(float v){
    float e = fast_ex2(-2.8853900817779268f * v);
    return fmaf(2.0f, fast_rcp(1.0f + e), -1.0f);
}

__device__ __forceinline__ void half_bar(int id){
    asm volatile("bar.sync %0, %1;" :: "r"(id), "r"(128) : "memory");
}

// Layer-0 GEMM, fully double-buffered (h AND weights one iteration ahead).
__device__ __forceinline__ void gemm_l0(ull acc[2][8], const float* __restrict__ WP,
                                        const float* __restrict__ hrow, int j0)
{
    const float* wp = WP + j0 * 2;
    ulonglong2 wa = *(const ulonglong2*)(wp);
    ulonglong2 wb = *(const ulonglong2*)(wp + 512);
    ulonglong2 hv[8];
    #pragma unroll
    for (int bb = 0; bb < 8; ++bb)
        hv[bb] = *(const ulonglong2*)(hrow + bb * 64);

    #pragma unroll
    for (int k4 = 0; k4 < 16; ++k4) {
        ulonglong2 hn[8];
        ulonglong2 wa_n, wb_n;
        if (k4 < 15) {
            #pragma unroll
            for (int bb = 0; bb < 8; ++bb)
                hn[bb] = *(const ulonglong2*)(hrow + bb * 64 + 4 * (k4 + 1));
            wa_n = *(const ulonglong2*)(wp + (k4 + 1) * 1024);
            wb_n = *(const ulonglong2*)(wp + (k4 + 1) * 1024 + 512);
        }

        #pragma unroll
        for (int bb = 0; bb < 8; ++bb) {
            acc[0][bb] = ffma2(hv[bb].x, wa.x, acc[0][bb]);
            acc[1][bb] = ffma2(hv[bb].x, wa.y, acc[1][bb]);
            acc[0][bb] = ffma2(hv[bb].y, wb.x, acc[0][bb]);
            acc[1][bb] = ffma2(hv[bb].y, wb.y, acc[1][bb]);
        }
        #pragma unroll
        for (int bb = 0; bb < 8; ++bb) hv[bb] = hn[bb];
        wa = wa_n; wb = wb_n;
    }
}

// Fused layer-1 GEMM: acc += h0.WI + h1.WH in one loop (64 FFMA2/iter).
// Weights double-buffered; h front-batched (16 loads ahead of 64 FMAs).
__device__ __forceinline__ void gemm_l1(ull acc[2][8],
                                        const float* __restrict__ WI, const float* __restrict__ WH,
                                        const float* __restrict__ h0r, const float* __restrict__ h1r,
                                        int j0)
{
    const float* wpI = WI + j0 * 2;
    const float* wpH = WH + j0 * 2;
    ulonglong2 wIa = *(const ulonglong2*)(wpI);
    ulonglong2 wIb = *(const ulonglong2*)(wpI + 512);
    ulonglong2 wHa = *(const ulonglong2*)(wpH);
    ulonglong2 wHb = *(const ulonglong2*)(wpH + 512);

    #pragma unroll
    for (int k4 = 0; k4 < 16; ++k4) {
        ulonglong2 h0v[8], h1v[8];
        #pragma unroll
        for (int bb = 0; bb < 8; ++bb) {
            h0v[bb] = *(const ulonglong2*)(h0r + bb * 64 + 4 * k4);
            h1v[bb] = *(const ulonglong2*)(h1r + bb * 64 + 4 * k4);
        }
        ulonglong2 wIa_n, wIb_n, wHa_n, wHb_n;
        if (k4 < 15) {
            wIa_n = *(const ulonglong2*)(wpI + (k4 + 1) * 1024);
            wIb_n = *(const ulonglong2*)(wpI + (k4 + 1) * 1024 + 512);
            wHa_n = *(const ulonglong2*)(wpH + (k4 + 1) * 1024);
            wHb_n = *(const ulonglong2*)(wpH + (k4 + 1) * 1024 + 512);
        }

        #pragma unroll
        for (int bb = 0; bb < 8; ++bb) {
            acc[0][bb] = ffma2(h0v[bb].x, wIa.x, acc[0][bb]);
            acc[1][bb] = ffma2(h0v[bb].x, wIa.y, acc[1][bb]);
            acc[0][bb] = ffma2(h0v[bb].y, wIb.x, acc[0][bb]);
            acc[1][bb] = ffma2(h0v[bb].y, wIb.y, acc[1][bb]);
        }
        #pragma unroll
        for (int bb = 0; bb < 8; ++bb) {
            acc[0][bb] = ffma2(h1v[bb].x, wHa.x, acc[0][bb]);
            acc[1][bb] = ffma2(h1v[bb].x, wHa.y, acc[1][bb]);
            acc[0][bb] = ffma2(h1v[bb].y, wHb.x, acc[0][bb]);
            acc[1][bb] = ffma2(h1v[bb].y, wHb.y, acc[1][bb]);
        }
        wIa = wIa_n; wIb = wIb_n; wHa = wHa_n; wHb = wHb_n;
    }
}

__global__ __launch_bounds__(NTHREADS)
void lstm2_fused_kernel(const float* __restrict__ x,
                        const float* __restrict__ w_ih0, const float* __restrict__ w_hh0,
                        const float* __restrict__ b_ih0, const float* __restrict__ b_hh0,
                        const float* __restrict__ w_ih1, const float* __restrict__ w_hh1,
                        const float* __restrict__ b_ih1, const float* __restrict__ b_hh1,
                        const float* __restrict__ w_fc,  const float* __restrict__ b_fc,
                        float* __restrict__ out)
{
    extern __shared__ float smem[];
    float* WP0  = smem + OFF_WP0;
    float* WPI1 = smem + OFF_WPI1;
    float* WPH1 = smem + OFF_WPH1;
    float* gbuf = smem + OFF_GB;
    float* h0s  = smem + OFF_H0;
    float* h1s  = smem + OFF_H1;
    float* xbuf = smem + OFF_XB;

    const int tid   = threadIdx.x;
    const int bbase = blockIdx.x * BB;

    for (int idx = tid; idx < 32 * 256; idx += NTHREADS) {
        int k2 = idx >> 8, j = idx & 255;
        float2 a0 = *(const float2*)(w_hh0 + j * 64 + 2 * k2);
        float2 a1 = *(const float2*)(w_ih1 + j * 64 + 2 * k2);
        float2 a2 = *(const float2*)(w_hh1 + j * 64 + 2 * k2);
        *(float2*)(WP0  + idx * 2) = a0;
        *(float2*)(WPI1 + idx * 2) = a1;
        *(float2*)(WPH1 + idx * 2) = a2;
    }
    for (int idx = tid; idx < BB * 64; idx += NTHREADS) { h0s[idx] = 0.0f; h1s[idx] = 0.0f; }
    if (tid < BB) xbuf[tid] = x[(bbase + tid) * TSEQ + 0];

    // half-CTA decomposition: warps 0-3 own bb 0-7, warps 4-7 own bb 8-15
    const int half = tid >> 7;
    const int l    = tid & 127;
    const int barid = half + 1;

    const int j0 = l * 2;
    const int g  = l >> 5;
    const float kexp = (g == 2) ? -2.8853900817779268f : -1.4426950408889634f;
    const float amul = (g == 2) ? 2.0f : 1.0f;
    const float aadd = (g == 2) ? -1.0f : 0.0f;

    float bias0c[2], bias1c[2], wi0c[2];
    #pragma unroll
    for (int c = 0; c < 2; ++c) {
        bias0c[c] = b_ih0[j0 + c] + b_hh0[j0 + c];
        bias1c[c] = b_ih1[j0 + c] + b_hh1[j0 + c];
        wi0c[c]   = w_ih0[j0 + c];
    }

    const int bb_u = half * 8 + (l >> 4);
    const int m_u  = (l & 15) * 4;
    float4 c0 = make_float4(0.f, 0.f, 0.f, 0.f);
    float4 c1 = make_float4(0.f, 0.f, 0.f, 0.f);

    const float* hrd0 = h0s + half * 512;
    const float* hrd1 = h1s + half * 512;
    float* gwr = gbuf + half * 8 * 256 + j0;
    const float* xrd = xbuf + half * 8;

    __syncthreads();

    for (int t = 0; t < TSEQ; ++t) {
        ull acc[2][8];

        // ---- layer 0 gates ----
        #pragma unroll
        for (int c = 0; c < 2; ++c)
            #pragma unroll
            for (int bb = 0; bb < 8; ++bb) acc[c][bb] = 0ULL;
        gemm_l0(acc, WP0, hrd0, j0);

        #pragma unroll
        for (int bb = 0; bb < 8; ++bb) {
            float xv = xrd[bb];
            float2 gv;
            float lo, hi;
            unpack2(acc[0][bb], lo, hi);
            float v0 = fmaf(xv, wi0c[0], bias0c[0]) + (lo + hi);
            unpack2(acc[1][bb], lo, hi);
            float v1 = fmaf(xv, wi0c[1], bias0c[1]) + (lo + hi);
            gv.x = fmaf(amul, fast_rcp(1.0f + fast_ex2(kexp * v0)), aadd);
            gv.y = fmaf(amul, fast_rcp(1.0f + fast_ex2(kexp * v1)), aadd);
            *(float2*)&gwr[bb * 256] = gv;
        }
        half_bar(barid);

        // ---- layer 0 state update ----
        {
            const float* gb = &gbuf[bb_u * 256 + m_u];
            float4 iv = *(const float4*)&gb[0];
            float4 fv = *(const float4*)&gb[64];
            float4 gv = *(const float4*)&gb[128];
            float4 ov = *(const float4*)&gb[192];
            c0.x = fmaf(fv.x, c0.x, iv.x * gv.x);
            c0.y = fmaf(fv.y, c0.y, iv.y * gv.y);
            c0.z = fmaf(fv.z, c0.z, iv.z * gv.z);
            c0.w = fmaf(fv.w, c0.w, iv.w * gv.w);
            float4 hv;
            hv.x = ov.x * tanh_(c0.x);
            hv.y = ov.y * tanh_(c0.y);
            hv.z = ov.z * tanh_(c0.z);
            hv.w = ov.w * tanh_(c0.w);
            *(float4*)&h0s[bb_u * 64 + m_u] = hv;
        }
        half_bar(barid);

        // ---- layer 1 gates (fused WI1 + WH1) ----
        #pragma unroll
        for (int c = 0; c < 2; ++c)
            #pragma unroll
            for (int bb = 0; bb < 8; ++bb) acc[c][bb] = 0ULL;
        gemm_l1(acc, WPI1, WPH1, hrd0, hrd1, j0);

        #pragma unroll
        for (int bb = 0; bb < 8; ++bb) {
            float2 gv;
            float lo, hi;
            unpack2(acc[0][bb], lo, hi);
            float v0 = bias1c[0] + (lo + hi);
            unpack2(acc[1][bb], lo, hi);
            float v1 = bias1c[1] + (lo + hi);
            gv.x = fmaf(amul, fast_rcp(1.0f + fast_ex2(kexp * v0)), aadd);
            gv.y = fmaf(amul, fast_rcp(1.0f + fast_ex2(kexp * v1)), aadd);
            *(float2*)&gwr[bb * 256] = gv;
        }
        half_bar(barid);

        // ---- layer 1 state update + x prefetch ----
        {
            const float* gb = &gbuf[bb_u * 256 + m_u];
            float4 iv = *(const float4*)&gb[0];
            float4 fv = *(const float4*)&gb[64];
            float4 gv = *(const float4*)&gb[128];
            float4 ov = *(const float4*)&gb[192];
            c1.x = fmaf(fv.x, c1.x, iv.x * gv.x);
            c1.y = fmaf(fv.y, c1.y, iv.y * gv.y);
            c1.z = fmaf(fv.z, c1.z, iv.z * gv.z);
            c1.w = fmaf(fv.w, c1.w, iv.w * gv.w);
            float4 hv;
            hv.x = ov.x * tanh_(c1.x);
            hv.y = ov.y * tanh_(c1.y);
            hv.z = ov.z * tanh_(c1.z);
            hv.w = ov.w * tanh_(c1.w);
            *(float4*)&h1s[bb_u * 64 + m_u] = hv;
        }
        if (t + 1 < TSEQ && l < 8)
            xbuf[half * 8 + l] = x[(bbase + half * 8 + l) * TSEQ + (t + 1)];
        half_bar(barid);
    }

    __syncthreads();

    // ---- final FC ----
    if (tid < BB * 3) {
        int bb  = tid / 3;
        int cls = tid - bb * 3;
        float s = b_fc[cls];
        #pragma unroll 8
        for (int m = 0; m < 64; ++m)
            s = fmaf(h1s[bb * 64 + m], w_fc[cls * 64 + m], s);
        out[(bbase + bb) * 3 + cls] = s;
    }
}

extern "C" void kernel_launch(void* const* d_in, const int* in_sizes, int n_in,
                              void* d_out, int out_size)
{
    const float* x     = (const float*)d_in[0];
    const float* w_ih0 = (const float*)d_in[1];
    const float* w_hh0 = (const float*)d_in[2];
    const float* b_ih0 = (const float*)d_in[3];
    const float* b_hh0 = (const float*)d_in[4];
    const float* w_ih1 = (const float*)d_in[5];
    const float* w_hh1 = (const float*)d_in[6];
    const float* b_ih1 = (const float*)d_in[7];
    const float* b_hh1 = (const float*)d_in[8];
    const float* w_fc  = (const float*)d_in[9];
    const float* b_fc  = (const float*)d_in[10];
    float* out = (float*)d_out;

    cudaFuncSetAttribute(lstm2_fused_kernel,
                         cudaFuncAttributeMaxDynamicSharedMemorySize, SMEM_BYTES);

    lstm2_fused_kernel<<<NBLOCKS, NTHREADS, SMEM_BYTES>>>(
        x, w_ih0, w_hh0, b_ih0, b_hh0,
        w_ih1, w_hh1, b_ih1, b_hh1,
        w_fc, b_fc, out);
}